// round 1
// baseline (speedup 1.0000x reference)
#include <cuda_runtime.h>
#include <math.h>

#define NTHREADS 128

__global__ __launch_bounds__(NTHREADS, 1)
void conv_policy_kernel(const float* __restrict__ x,
                        const float* __restrict__ c1w, const float* __restrict__ c1b,
                        const float* __restrict__ c2w, const float* __restrict__ c2b,
                        const float* __restrict__ c3w, const float* __restrict__ c3b,
                        const float* __restrict__ e1w, const float* __restrict__ e1b,
                        const float* __restrict__ e2w, const float* __restrict__ e2b,
                        const float* __restrict__ d1w, const float* __restrict__ d1b,
                        const float* __restrict__ d2w, const float* __restrict__ d2b,
                        const float* __restrict__ d3w, const float* __restrict__ d3b,
                        const float* __restrict__ d4w, const float* __restrict__ d4b,
                        float* __restrict__ out)
{
    __shared__ float jcat[12][15];   // [jl(6); jdl(6)] x 15
    __shared__ float fm1[6][13];     // conv1 out (tanh)
    __shared__ float fm1ds[6][5];    // adaptive-pool 13->5
    __shared__ float fm2[4][5];      // conv2 out (len 3, padded array)
    __shared__ float embin[6];       // [conv3/fm_links(4); psi; obsd_last]
    __shared__ float emb1[4];
    __shared__ float emb2[4];
    __shared__ float dc1[4][3];      // dec1 out
    __shared__ float dc2[2][5];      // dec2 out
    __shared__ float dc3[2][15];     // dec3 out (after fused upsample)

    const int t = threadIdx.x;

    // ---- build jcat: channels 0-5 = [0,0,x[7..94]], 6-11 = [0,0,x[101..188]]
    for (int idx = t; idx < 180; idx += NTHREADS) {
        int c = idx / 15, l = idx % 15;
        float v;
        if (c < 6) {
            int j = c * 15 + l;                 // 0..89
            v = (j < 2) ? 0.0f : x[7 + j - 2];
        } else {
            int j = (c - 6) * 15 + l;
            v = (j < 2) ? 0.0f : x[101 + j - 2];
        }
        jcat[c][l] = v;
    }
    __syncthreads();

    // ---- conv1: in (12,15) k=3 pad=0 -> (6,13), tanh
    for (int idx = t; idx < 78; idx += NTHREADS) {
        int o = idx / 13, l = idx % 13;
        float s = c1b[o];
        #pragma unroll
        for (int i = 0; i < 12; i++) {
            #pragma unroll
            for (int h = 0; h < 3; h++)
                s = fmaf(c1w[(o * 12 + i) * 3 + h], jcat[i][l + h], s);
        }
        fm1[o][l] = tanhf(s);
    }
    __syncthreads();

    // ---- adaptive avg pool 13 -> 5
    if (t < 30) {
        int o = t / 5, p = t % 5;
        const int S[5] = {0, 2, 5, 7, 10};
        const int E[5] = {3, 6, 8, 11, 13};
        float s = 0.0f;
        for (int l = S[p]; l < E[p]; l++) s += fm1[o][l];
        fm1ds[o][p] = s / (float)(E[p] - S[p]);
    }
    __syncthreads();

    // ---- conv2: in (6,5) k=3 pad=0 -> (4,3), tanh
    if (t < 12) {
        int o = t / 3, l = t % 3;
        float s = c2b[o];
        #pragma unroll
        for (int i = 0; i < 6; i++) {
            #pragma unroll
            for (int h = 0; h < 3; h++)
                s = fmaf(c2w[(o * 6 + i) * 3 + h], fm1ds[i][l + h], s);
        }
        fm2[o][l] = tanhf(s);
    }
    __syncthreads();

    // ---- conv3: in (4,3) k=3 pad=0 -> (4,1), tanh. fm_links = mean(len 1) = same.
    if (t < 4) {
        float s = c3b[t];
        #pragma unroll
        for (int i = 0; i < 4; i++) {
            #pragma unroll
            for (int h = 0; h < 3; h++)
                s = fmaf(c3w[(t * 4 + i) * 3 + h], fm2[i][h], s);
        }
        embin[t] = tanhf(s);
    }
    if (t == 0) {
        float qw = x[3], qx = x[4], qy = x[5], qz = x[6];
        embin[4] = atan2f(qz, qw) - atan2f(-qx, qy);  // psi
        embin[5] = x[100];                            // obsd[:, -1]
    }
    __syncthreads();

    // ---- emb1 (1x1 conv, 6->4), tanh
    if (t < 4) {
        float s = e1b[t];
        #pragma unroll
        for (int i = 0; i < 6; i++) s = fmaf(e1w[t * 6 + i], embin[i], s);
        emb1[t] = tanhf(s);
    }
    __syncthreads();

    // ---- emb2 (1x1 conv, 4->4), tanh
    if (t < 4) {
        float s = e2b[t];
        #pragma unroll
        for (int i = 0; i < 4; i++) s = fmaf(e2w[t * 4 + i], emb1[i], s);
        emb2[t] = tanhf(s);
    }
    __syncthreads();

    // ---- dec1: convT (4->4, k=3, pad=0), in len 1 -> out len 3
    // y[o][t] = b[o] + sum_i w[i][o][t] * x[i][0]
    if (t < 12) {
        int o = t / 3, l = t % 3;
        float s = d1b[o];
        #pragma unroll
        for (int i = 0; i < 4; i++)
            s = fmaf(d1w[(i * 4 + o) * 3 + l], emb2[i], s);
        dc1[o][l] = tanhf(s);
    }
    __syncthreads();

    // ---- dec2: convT (4->2, k=3, pad=0), in len 3 -> out len 5
    // y[o][t] = b[o] + sum_i sum_h w[i][o][h] * in[i][t-h], 0<=t-h<3
    if (t < 10) {
        int o = t / 5, l = t % 5;
        float s = d2b[o];
        #pragma unroll
        for (int i = 0; i < 4; i++) {
            #pragma unroll
            for (int h = 0; h < 3; h++) {
                int p = l - h;
                if (p >= 0 && p < 3)
                    s = fmaf(d2w[(i * 2 + o) * 3 + h], dc1[i][p], s);
            }
        }
        dc2[o][l] = tanhf(s);
    }
    __syncthreads();

    // ---- upsample (UP_IDX) fused into dec3: convT (2->2, k=3, pad=0), in len 13 -> 15
    if (t < 30) {
        const int UP[13] = {0, 0, 0, 1, 1, 1, 2, 2, 3, 3, 3, 4, 4};
        int o = t / 15, l = t % 15;
        float s = d3b[o];
        #pragma unroll
        for (int i = 0; i < 2; i++) {
            #pragma unroll
            for (int h = 0; h < 3; h++) {
                int p = l - h;
                if (p >= 0 && p < 13)
                    s = fmaf(d3w[(i * 2 + o) * 3 + h], dc2[i][UP[p]], s);
            }
        }
        dc3[o][l] = tanhf(s);
    }
    __syncthreads();

    // ---- dec4: convT (14->6, k=3, pad=1), in (14,15)=[dc3(2); jcat(12)] -> (6,15)
    // y[o][t] = b[o] + sum_i sum_h w[i][o][h] * in[i][t-h+1], 0<=t-h+1<15
    // output: flatten (6,15)=90, drop first 2 -> 88
    if (t < 88) {
        int g = t + 2;
        int o = g / 15, l = g % 15;
        float s = d4b[o];
        #pragma unroll
        for (int h = 0; h < 3; h++) {
            int p = l - h + 1;
            if (p >= 0 && p < 15) {
                #pragma unroll
                for (int i = 0; i < 14; i++) {
                    float v = (i < 2) ? dc3[i][p] : jcat[i - 2][p];
                    s = fmaf(d4w[(i * 6 + o) * 3 + h], v, s);
                }
            }
        }
        out[t] = s;
    }
}

extern "C" void kernel_launch(void* const* d_in, const int* in_sizes, int n_in,
                              void* d_out, int out_size) {
    (void)in_sizes; (void)n_in; (void)out_size;
    conv_policy_kernel<<<1, NTHREADS>>>(
        (const float*)d_in[0],
        (const float*)d_in[1],  (const float*)d_in[2],
        (const float*)d_in[3],  (const float*)d_in[4],
        (const float*)d_in[5],  (const float*)d_in[6],
        (const float*)d_in[7],  (const float*)d_in[8],
        (const float*)d_in[9],  (const float*)d_in[10],
        (const float*)d_in[11], (const float*)d_in[12],
        (const float*)d_in[13], (const float*)d_in[14],
        (const float*)d_in[15], (const float*)d_in[16],
        (const float*)d_in[17], (const float*)d_in[18],
        (float*)d_out);
}